// round 5
// baseline (speedup 1.0000x reference)
#include <cuda_runtime.h>
#include <cuda_fp16.h>
#include <cstdint>

// ---------------------------------------------------------------------------
// GCN: out = SpMM(relu(SpMM(X@W1+b1)) @ W2 + b2)
// R5: fused single-block scan, vectorized hist/scatter, register-prefetch
//     double-buffered HMMA GEMMs, 8-deep unrolled fp16 CSR SpMM.
// ---------------------------------------------------------------------------

#define MAX_NODES 100000
#define MAX_EDGES 1600000
#define FEAT 128

// Scratch
__device__ __align__(16) __half g_H [(size_t)MAX_NODES * FEAT];  // GEMM out (fp16)
__device__ __align__(16) __half g_S1[(size_t)MAX_NODES * FEAT];  // relu(SpMM1) (fp16)
__device__ int  g_cnt[MAX_NODES];
__device__ int  g_row_start[MAX_NODES + 1];
__device__ int  g_row_next[MAX_NODES];
__device__ int2 g_edge[MAX_EDGES];                 // {col, float_as_int(val)}

// ---------------------------------------------------------------------------
// CSR build: zero -> hist (vec4) -> fused scan -> scatter (vec4)
// ---------------------------------------------------------------------------
__global__ void zero_cnt_kernel(int4* __restrict__ cnt4, int n4)
{
    int i = blockIdx.x * blockDim.x + threadIdx.x;
    if (i < n4) cnt4[i] = make_int4(0, 0, 0, 0);
}

__global__ void hist_kernel(const int4* __restrict__ row4, int nE4, int* __restrict__ cnt)
{
    int i = blockIdx.x * blockDim.x + threadIdx.x;
    if (i < nE4) {
        int4 r = row4[i];
        atomicAdd(&cnt[r.x], 1);
        atomicAdd(&cnt[r.y], 1);
        atomicAdd(&cnt[r.z], 1);
        atomicAdd(&cnt[r.w], 1);
    }
}

// Single-block exclusive scan of cnt[0..n) -> row_start / row_next, total -> row_start[n].
__global__ __launch_bounds__(1024) void scan_fused_kernel(
    const int* __restrict__ cnt, int* __restrict__ row_start,
    int* __restrict__ row_next, int n)
{
    __shared__ int sh[1024];
    const int tid   = threadIdx.x;
    const int CHUNK = (n + 1023) >> 10;
    const int start = tid * CHUNK;
    const int end   = min(start + CHUNK, n);

    int sum = 0;
    for (int i = start; i < end; i++) sum += cnt[i];
    sh[tid] = sum;
    __syncthreads();
#pragma unroll
    for (int off = 1; off < 1024; off <<= 1) {
        int t = (tid >= off) ? sh[tid - off] : 0;
        __syncthreads();
        sh[tid] += t;
        __syncthreads();
    }
    int run = sh[tid] - sum;              // exclusive prefix
    for (int i = start; i < end; i++) {
        int c = cnt[i];
        row_start[i] = run;
        row_next[i]  = run;
        run += c;
    }
    if (tid == 1023) row_start[n] = run;  // grand total
}

__global__ void scatter_kernel(const int4* __restrict__ row4, const int4* __restrict__ col4,
                               const float4* __restrict__ vals4, int nE4,
                               int* __restrict__ row_next, int2* __restrict__ edge)
{
    int i = blockIdx.x * blockDim.x + threadIdx.x;
    if (i < nE4) {
        int4   r = row4[i];
        int4   c = col4[i];
        float4 v = vals4[i];
        int p0 = atomicAdd(&row_next[r.x], 1);
        edge[p0] = make_int2(c.x, __float_as_int(v.x));
        int p1 = atomicAdd(&row_next[r.y], 1);
        edge[p1] = make_int2(c.y, __float_as_int(v.y));
        int p2 = atomicAdd(&row_next[r.z], 1);
        edge[p2] = make_int2(c.z, __float_as_int(v.z));
        int p3 = atomicAdd(&row_next[r.w], 1);
        edge[p3] = make_int2(c.w, __float_as_int(v.w));
    }
}

// ---------------------------------------------------------------------------
// HMMA GEMM: C_h[M,128] = (A[M,K] @ W[K,128] + bias), fp16 out, fp32 accum.
// 256 threads = 8 warps (4x2), BM=128, BK=32, warp tile 32x64.
// Register-prefetch + 2-deep smem ping-pong: one __syncthreads per k-tile.
// ---------------------------------------------------------------------------
__device__ __forceinline__ void mma16816(float* d, const uint32_t* a, const uint32_t* b)
{
    asm volatile(
        "mma.sync.aligned.m16n8k16.row.col.f32.f16.f16.f32 "
        "{%0,%1,%2,%3}, {%4,%5,%6,%7}, {%8,%9}, {%0,%1,%2,%3};\n"
        : "+f"(d[0]), "+f"(d[1]), "+f"(d[2]), "+f"(d[3])
        : "r"(a[0]), "r"(a[1]), "r"(a[2]), "r"(a[3]), "r"(b[0]), "r"(b[1]));
}

__device__ __forceinline__ void ldsm_x4(uint32_t* r, uint32_t addr)
{
    asm volatile("ldmatrix.sync.aligned.m8n8.x4.shared.b16 {%0,%1,%2,%3}, [%4];"
                 : "=r"(r[0]), "=r"(r[1]), "=r"(r[2]), "=r"(r[3]) : "r"(addr));
}

__device__ __forceinline__ void ldsm_x4_t(uint32_t* r, uint32_t addr)
{
    asm volatile("ldmatrix.sync.aligned.m8n8.x4.trans.shared.b16 {%0,%1,%2,%3}, [%4];"
                 : "=r"(r[0]), "=r"(r[1]), "=r"(r[2]), "=r"(r[3]) : "r"(addr));
}

#define AS_STRIDE 56   // halves; 112B rows: 16B-aligned, ldmatrix conflict-limited
#define WS_STRIDE 136  // halves; 272B rows

template <int K, bool A_HALF>
__global__ __launch_bounds__(256) void gemm_hmma_kernel(
    const void* __restrict__ A_, const float* __restrict__ W,
    const float* __restrict__ bias, __half* __restrict__ C, int M)
{
    constexpr int BM = 128, BK = 32, N = 128;
    constexpr int T = K / BK;
    __shared__ __half As[2][BM * AS_STRIDE];
    __shared__ __half Ws[2][BK * WS_STRIDE];

    const int tid  = threadIdx.x;
    const int lane = tid & 31;
    const int wid  = tid >> 5;
    const int wm   = wid >> 1;
    const int wn   = wid & 1;
    const int m0   = blockIdx.x * BM;

    float acc[2][8][4];
#pragma unroll
    for (int i = 0; i < 2; i++)
#pragma unroll
        for (int j = 0; j < 8; j++)
#pragma unroll
            for (int q = 0; q < 4; q++) acc[i][j][q] = 0.f;

    const uint32_t sAs0 = (uint32_t)__cvta_generic_to_shared(&As[0][0]);
    const uint32_t sAs1 = (uint32_t)__cvta_generic_to_shared(&As[1][0]);
    const uint32_t sWs0 = (uint32_t)__cvta_generic_to_shared(&Ws[0][0]);
    const uint32_t sWs1 = (uint32_t)__cvta_generic_to_shared(&Ws[1][0]);

    // staged-load registers
    float4 raf[4];   // GEMM1: fp32 A (4 x float4)
    uint4  rah[2];   // GEMM2: fp16 A (2 x uint4)
    float4 rwf[4];   // W fp32 (4 x float4)

    auto ld_tile = [&](int t) {
        const int k0 = t * BK;
        if (A_HALF) {
            const __half* A = (const __half*)A_;
#pragma unroll
            for (int i = 0; i < 2; i++) {
                int idx = tid + i * 256;
                int rr = idx >> 2, cc = (idx & 3) << 3;
                int gr = m0 + rr;
                rah[i] = make_uint4(0, 0, 0, 0);
                if (gr < M) rah[i] = *(const uint4*)(A + (size_t)gr * K + k0 + cc);
            }
        } else {
            const float* A = (const float*)A_;
#pragma unroll
            for (int i = 0; i < 4; i++) {
                int idx = tid + i * 256;
                int rr = idx >> 3, cc = (idx & 7) << 2;
                int gr = m0 + rr;
                raf[i] = make_float4(0.f, 0.f, 0.f, 0.f);
                if (gr < M) raf[i] = *(const float4*)(A + (size_t)gr * K + k0 + cc);
            }
        }
#pragma unroll
        for (int i = 0; i < 4; i++) {
            int idx = tid + i * 256;
            int rr = idx >> 5, cc = (idx & 31) << 2;
            rwf[i] = *(const float4*)(W + (size_t)(k0 + rr) * N + cc);
        }
    };

    auto st_tile = [&](int b) {
        if (A_HALF) {
#pragma unroll
            for (int i = 0; i < 2; i++) {
                int idx = tid + i * 256;
                int rr = idx >> 2, cc = (idx & 3) << 3;
                *(uint4*)(&As[b][rr * AS_STRIDE + cc]) = rah[i];
            }
        } else {
#pragma unroll
            for (int i = 0; i < 4; i++) {
                int idx = tid + i * 256;
                int rr = idx >> 3, cc = (idx & 7) << 2;
                __half2* dst = (__half2*)(&As[b][rr * AS_STRIDE + cc]);
                dst[0] = __floats2half2_rn(raf[i].x, raf[i].y);
                dst[1] = __floats2half2_rn(raf[i].z, raf[i].w);
            }
        }
#pragma unroll
        for (int i = 0; i < 4; i++) {
            int idx = tid + i * 256;
            int rr = idx >> 5, cc = (idx & 31) << 2;
            __half2* dst = (__half2*)(&Ws[b][rr * WS_STRIDE + cc]);
            dst[0] = __floats2half2_rn(rwf[i].x, rwf[i].y);
            dst[1] = __floats2half2_rn(rwf[i].z, rwf[i].w);
        }
    };

    ld_tile(0);
    st_tile(0);
    __syncthreads();

    for (int t = 0; t < T; t++) {
        if (t + 1 < T) ld_tile(t + 1);          // prefetch next tile into regs
        const uint32_t sAs = (t & 1) ? sAs1 : sAs0;
        const uint32_t sWs = (t & 1) ? sWs1 : sWs0;
#pragma unroll
        for (int ks = 0; ks < 2; ks++) {
            const int kk = ks * 16;
            uint32_t a[2][4], b[4][4];
#pragma unroll
            for (int mi = 0; mi < 2; mi++) {
                int r0 = wm * 32 + mi * 16;
                uint32_t addr = sAs + ((r0 + (lane & 15)) * AS_STRIDE
                                       + kk + ((lane >> 4) << 3)) * 2;
                ldsm_x4(a[mi], addr);
            }
#pragma unroll
            for (int p = 0; p < 4; p++) {
                int c0 = wn * 64 + p * 16;
                uint32_t addr = sWs + ((kk + (lane & 15)) * WS_STRIDE
                                       + c0 + ((lane >> 4) << 3)) * 2;
                ldsm_x4_t(b[p], addr);
            }
#pragma unroll
            for (int mi = 0; mi < 2; mi++)
#pragma unroll
                for (int p = 0; p < 4; p++) {
                    mma16816(acc[mi][2 * p],     a[mi], &b[p][0]);
                    mma16816(acc[mi][2 * p + 1], a[mi], &b[p][2]);
                }
        }
        if (t + 1 < T) {
            __syncthreads();                    // everyone done reading buf (t+1)&1
            st_tile((t + 1) & 1);
            __syncthreads();
        }
    }

    // epilogue: +bias, fp16 store
    const int rq = lane >> 2;
    const int cq = (lane & 3) << 1;
#pragma unroll
    for (int ni = 0; ni < 8; ni++) {
        int gc = wn * 64 + ni * 8 + cq;
        float2 bb = *(const float2*)(bias + gc);
#pragma unroll
        for (int mi = 0; mi < 2; mi++) {
            int r_base = m0 + wm * 32 + mi * 16 + rq;
            float* d = acc[mi][ni];
            if (r_base < M)
                *(__half2*)(C + (size_t)r_base * N + gc) =
                    __floats2half2_rn(d[0] + bb.x, d[1] + bb.y);
            if (r_base + 8 < M)
                *(__half2*)(C + (size_t)(r_base + 8) * N + gc) =
                    __floats2half2_rn(d[2] + bb.x, d[3] + bb.y);
        }
    }
}

// ---------------------------------------------------------------------------
// CSR SpMM over fp16 H: warp per row, lane l owns features [4l..4l+3].
// 8-deep unrolled gather (MLP=8). OUT_HALF_RELU: fp16+relu (L1) vs fp32 (L2).
// ---------------------------------------------------------------------------
template <bool OUT_HALF_RELU>
__global__ __launch_bounds__(256) void spmm_csr_kernel(
    const int* __restrict__ row_start, const int2* __restrict__ edge,
    const __half* __restrict__ H, void* __restrict__ out_, int n)
{
    int r    = blockIdx.x * 8 + (threadIdx.x >> 5);
    int lane = threadIdx.x & 31;
    if (r >= n) return;

    int s = row_start[r];
    int e = row_start[r + 1];

    float4 acc = make_float4(0.f, 0.f, 0.f, 0.f);
    const int fo = lane << 2;

    auto fma_edge = [&](int2 ev) {
        float v = __int_as_float(ev.y);
        uint2 u = __ldg((const uint2*)(H + (size_t)ev.x * FEAT + fo));
        float2 h01 = __half22float2(*(const __half2*)&u.x);
        float2 h23 = __half22float2(*(const __half2*)&u.y);
        acc.x += v * h01.x; acc.y += v * h01.y;
        acc.z += v * h23.x; acc.w += v * h23.y;
    };

    int i = s;
    for (; i + 8 <= e; i += 8) {
        int2 ev[8];
#pragma unroll
        for (int j = 0; j < 8; j++) ev[j] = edge[i + j];
#pragma unroll
        for (int j = 0; j < 8; j++) fma_edge(ev[j]);
    }
    for (; i + 2 <= e; i += 2) {
        int2 e0 = edge[i], e1 = edge[i + 1];
        fma_edge(e0); fma_edge(e1);
    }
    if (i < e) fma_edge(edge[i]);

    if (OUT_HALF_RELU) {
        __half* out = (__half*)out_;
        uint2 o;
        *(__half2*)&o.x = __floats2half2_rn(fmaxf(acc.x, 0.f), fmaxf(acc.y, 0.f));
        *(__half2*)&o.y = __floats2half2_rn(fmaxf(acc.z, 0.f), fmaxf(acc.w, 0.f));
        *(uint2*)(out + (size_t)r * FEAT + fo) = o;
    } else {
        float* out = (float*)out_;
        *(float4*)(out + (size_t)r * FEAT + fo) = acc;
    }
}

// ---------------------------------------------------------------------------
extern "C" void kernel_launch(void* const* d_in, const int* in_sizes, int n_in,
                              void* d_out, int out_size)
{
    const float* X    = (const float*)d_in[0];
    const float* W1   = (const float*)d_in[1];
    const float* b1   = (const float*)d_in[2];
    const float* W2   = (const float*)d_in[3];
    const float* b2   = (const float*)d_in[4];
    const float* vals = (const float*)d_in[5];
    const int*   row  = (const int*)d_in[6];
    const int*   col  = (const int*)d_in[7];

    const int M  = in_sizes[0] / 256;   // 100000
    const int nE = in_sizes[5];         // 1600000 (divisible by 4)

    __half *H, *S1;
    int *cnt, *row_start, *row_next;
    int2 *edge;
    cudaGetSymbolAddress((void**)&H,         g_H);
    cudaGetSymbolAddress((void**)&S1,        g_S1);
    cudaGetSymbolAddress((void**)&cnt,       g_cnt);
    cudaGetSymbolAddress((void**)&row_start, g_row_start);
    cudaGetSymbolAddress((void**)&row_next,  g_row_next);
    cudaGetSymbolAddress((void**)&edge,      g_edge);
    float* out = (float*)d_out;

    static cudaStream_t s_side = nullptr;
    static cudaEvent_t  ev_fork = nullptr, ev_join = nullptr;
    if (s_side == nullptr) {
        cudaStreamCreateWithFlags(&s_side, cudaStreamNonBlocking);
        cudaEventCreateWithFlags(&ev_fork, cudaEventDisableTiming);
        cudaEventCreateWithFlags(&ev_join, cudaEventDisableTiming);
    }

    // Fork: CSR build on side stream, concurrent with GEMM1.
    cudaEventRecord(ev_fork, 0);
    cudaStreamWaitEvent(s_side, ev_fork, 0);

    const int n4  = (M + 3) / 4;
    const int nE4 = nE / 4;
    zero_cnt_kernel<<<(n4 + 511) / 512, 512, 0, s_side>>>((int4*)cnt, n4);
    hist_kernel<<<(nE4 + 255) / 256, 256, 0, s_side>>>((const int4*)row, nE4, cnt);
    scan_fused_kernel<<<1, 1024, 0, s_side>>>(cnt, row_start, row_next, M);
    scatter_kernel<<<(nE4 + 255) / 256, 256, 0, s_side>>>(
        (const int4*)row, (const int4*)col, (const float4*)vals, nE4, row_next, edge);
    cudaEventRecord(ev_join, s_side);

    // Main stream: GEMM1 (X fp32 -> H fp16).
    const int gemm_blocks = (M + 127) / 128;
    gemm_hmma_kernel<256, false><<<gemm_blocks, 256>>>(X, W1, b1, H, M);

    cudaStreamWaitEvent(0, ev_join, 0);
    spmm_csr_kernel<true><<<(M + 7) / 8, 256>>>(row_start, edge, H, S1, M);
    gemm_hmma_kernel<128, true><<<gemm_blocks, 256>>>(S1, W2, b2, H, M);
    spmm_csr_kernel<false><<<(M + 7) / 8, 256>>>(row_start, edge, H, out, M);
}